// round 7
// baseline (speedup 1.0000x reference)
#include <cuda_runtime.h>
#include <cuda_bf16.h>

// SudokuDigitsDoubles — exact boolean reduction ("naked pairs" row elimination).
//
// Per (puzzle b, row r):
//   m[c]   = 9-bit candidate mask of cell c
//   pv[c]  = m[c] if popcount(m[c]) == 2 else 0
//   active pattern: appears exactly twice among pv[0..8]
//   erase[c] = OR of active patterns p with p != pv[c]
//   out bit (d,c) = m[c] & ~erase[c]
//
// Round 7: warp-autonomous. One warp == one puzzle, private smem slice,
// __syncwarp-only synchronization (no CTA barriers). 64 independent warps
// per SM keep the DRAM request stream smooth instead of the barrier-convoyed
// bursts of rounds 1-6. Access pattern per warp is the proven coalesced
// per-digit strided layout; candidate bit = float bit 23 (1.0f vs 0.0f).

static constexpr int PUZ = 729;        // 9 digits * 81 cells
static constexpr int WARPS = 8;        // puzzles per block
static constexpr int THREADS = WARPS * 32;
static constexpr int SLICE = 88;       // 81 used + pad

__global__ __launch_bounds__(THREADS, 8)
void sudoku_doubles_kernel(const float* __restrict__ in,
                           float* __restrict__ out,
                           int nPuz)
{
    __shared__ int masks[WARPS][SLICE];

    const int wid  = threadIdx.x >> 5;
    const int lane = threadIdx.x & 31;
    const int puz  = blockIdx.x * WARPS + wid;
    if (puz >= nPuz) return;            // warp-uniform

    const float* pin  = in  + (size_t)puz * PUZ;
    float*       pout = out + (size_t)puz * PUZ;
    int* mslice = masks[wid];

    // ---- Phase 1: build 9-bit candidate masks (27 independent coalesced LDGs/lane) ----
    #pragma unroll
    for (int i = 0; i < 3; i++) {
        const int cell = lane + 32 * i;
        if (cell < 81) {
            unsigned m = 0;
            #pragma unroll
            for (int d = 0; d < 9; d++)
                m |= ((__float_as_uint(pin[d * 81 + cell]) >> 23) & 1u) << d;
            mslice[cell] = (int)m;
        }
    }
    __syncwarp();

    // ---- Phase 2: 9 leader lanes do the row logic, write keep masks in place ----
    if (lane < 9) {
        const int base = lane * 9;
        int m[9], pv[9];
        #pragma unroll
        for (int c = 0; c < 9; c++) {
            m[c]  = mslice[base + c];
            pv[c] = (__popc(m[c]) == 2) ? m[c] : 0;
        }
        int act = 0, tor = 0;
        #pragma unroll
        for (int j = 0; j < 9; j++) {
            int cc = 0;
            #pragma unroll
            for (int k = 0; k < 9; k++)
                cc += (pv[k] == pv[j]) ? 1 : 0;
            const bool a = (pv[j] != 0) & (cc == 2);
            act |= a ? (1 << j) : 0;
            tor |= a ? pv[j] : 0;
        }
        #pragma unroll
        for (int c = 0; c < 9; c++) {
            int erase;
            if ((act >> c) & 1) {
                // rare: this cell holds an active pair -> exclude its own pattern
                erase = 0;
                #pragma unroll
                for (int j = 0; j < 9; j++)
                    if (((act >> j) & 1) && pv[j] != pv[c])
                        erase |= pv[j];
            } else {
                erase = tor;
            }
            mslice[base + c] = m[c] & ~erase;   // now holds keep mask
        }
    }
    __syncwarp();

    // ---- Phase 3: expand keep masks to floats (27 coalesced STGs/lane) ----
    #pragma unroll
    for (int i = 0; i < 3; i++) {
        const int cell = lane + 32 * i;
        if (cell < 81) {
            const int keep = mslice[cell];
            #pragma unroll
            for (int d = 0; d < 9; d++)
                pout[d * 81 + cell] = ((keep >> d) & 1) ? 1.0f : 0.0f;
        }
    }
}

extern "C" void kernel_launch(void* const* d_in, const int* in_sizes, int n_in,
                              void* d_out, int out_size)
{
    const float* mask = (const float*)d_in[0];
    float* out = (float*)d_out;
    const int nPuz = in_sizes[0] / PUZ;   // 32768
    const int grid = (nPuz + WARPS - 1) / WARPS;
    sudoku_doubles_kernel<<<grid, THREADS>>>(mask, out, nPuz);
}

// round 8
// speedup vs baseline: 1.5109x; 1.5109x over previous
#include <cuda_runtime.h>
#include <cuda_bf16.h>
#include <cstdint>

// SudokuDigitsDoubles — exact boolean reduction ("naked pairs" row elimination).
//
// Round 8: bulk-async I/O. Each block moves its 8-puzzle tile (23328 B) with
// ONE cp.async.bulk G->S, builds 9-bit cell masks from smem, 72 leader lanes
// run the pair logic and edit the smem tile in place (only ~0.36 rows/block
// ever change), then ONE cp.async.bulk S->G writes the tile out. Per-element
// LDG/STG instructions are gone; the LSU stream is ~5x smaller than R5.

static constexpr int PUZ = 729;               // floats per puzzle
static constexpr int PPB = 8;                 // puzzles per block
static constexpr int NF = PPB * PUZ;          // 5832 floats
static constexpr unsigned TILE_BYTES = NF * 4;  // 23328 (16B multiple)
static constexpr int NCELL = PPB * 81;        // 648
static constexpr int THREADS = 256;

__device__ __forceinline__ unsigned smem_u32(const void* p) {
    unsigned a;
    asm("{ .reg .u64 t; cvta.to.shared.u64 t, %1; cvt.u32.u64 %0, t; }"
        : "=r"(a) : "l"(p));
    return a;
}

__global__ __launch_bounds__(THREADS, 8)
void sudoku_doubles_kernel(const float* __restrict__ in,
                           float* __restrict__ out,
                           int nPuz)
{
    __shared__ alignas(128) float tile[NF];
    __shared__ int masks[NCELL];
    __shared__ alignas(8) unsigned long long mbar;

    const int basePuz = blockIdx.x * PPB;
    const bool full = (basePuz + PPB <= nPuz);
    const unsigned tid = threadIdx.x;

    if (full) {
        const unsigned sTile = smem_u32(tile);
        const unsigned sBar  = smem_u32(&mbar);
        const float* gsrc = in  + (size_t)basePuz * PUZ;
        float*       gdst = out + (size_t)basePuz * PUZ;

        // ---- bulk async load: gmem -> smem (one instruction) ----
        if (tid == 0) {
            asm volatile("mbarrier.init.shared.b64 [%0], 1;" :: "r"(sBar) : "memory");
        }
        __syncthreads();
        if (tid == 0) {
            asm volatile("mbarrier.arrive.expect_tx.shared.b64 _, [%0], %1;"
                         :: "r"(sBar), "r"(TILE_BYTES) : "memory");
            asm volatile(
                "cp.async.bulk.shared::cluster.global.mbarrier::complete_tx::bytes "
                "[%0], [%1], %2, [%3];"
                :: "r"(sTile), "l"(gsrc), "r"(TILE_BYTES), "r"(sBar) : "memory");
        }
        // all threads wait for tile arrival (acquire orders subsequent LDS)
        {
            unsigned done;
            do {
                asm volatile(
                    "{\n\t.reg .pred p;\n\t"
                    "mbarrier.try_wait.parity.acquire.cta.shared::cta.b64 p, [%1], %2;\n\t"
                    "selp.b32 %0, 1, 0, p;\n\t}"
                    : "=r"(done) : "r"(sBar), "r"(0u) : "memory");
            } while (!done);
        }

        // ---- B1: build 9-bit candidate masks from smem floats (conflict-free LDS) ----
        #pragma unroll
        for (int it = 0; it < 3; ++it) {
            const int t = tid + it * THREADS;
            if (t < NCELL) {
                const int pl = t / 81;
                const int rc = t - pl * 81;
                const float* p = tile + pl * PUZ + rc;
                unsigned m = 0;
                #pragma unroll
                for (int d = 0; d < 9; d++)
                    m |= ((__float_as_uint(p[d * 81]) >> 23) & 1u) << d;  // 1.0f vs 0.0f
                masks[t] = (int)m;
            }
        }
        __syncthreads();

        // ---- B2: 72 row leaders; rows with an active pair edit the smem tile ----
        if (tid < PPB * 9) {
            const int rowBase = 9 * tid;       // masks index (tid = pl*9 + r)
            int m[9], pv[9];
            #pragma unroll
            for (int c = 0; c < 9; c++) {
                m[c]  = masks[rowBase + c];
                pv[c] = (__popc(m[c]) == 2) ? m[c] : 0;
            }
            int act = 0, tor = 0;
            #pragma unroll
            for (int j = 0; j < 9; j++) {
                int cc = 0;
                #pragma unroll
                for (int k = 0; k < 9; k++)
                    cc += (pv[k] == pv[j]) ? 1 : 0;
                const bool a = (pv[j] != 0) & (cc == 2);
                act |= a ? (1 << j) : 0;
                tor |= a ? pv[j] : 0;
            }
            if (act) {                          // rare: ~0.5% of rows
                const int pl = tid / 9;
                const int r  = tid - 9 * pl;
                float* o = tile + pl * PUZ + r * 9;
                #pragma unroll
                for (int c = 0; c < 9; c++) {
                    int erase;
                    if ((act >> c) & 1) {
                        erase = 0;
                        #pragma unroll
                        for (int j = 0; j < 9; j++)
                            if (((act >> j) & 1) && pv[j] != pv[c])
                                erase |= pv[j];
                    } else {
                        erase = tor;
                    }
                    const int keep = m[c] & ~erase;
                    #pragma unroll
                    for (int d = 0; d < 9; d++)
                        o[d * 81 + c] = ((keep >> d) & 1) ? 1.0f : 0.0f;
                }
            }
        }
        __syncthreads();

        // ---- bulk async store: smem -> gmem (one instruction) ----
        if (tid == 0) {
            asm volatile("fence.proxy.async.shared::cta;" ::: "memory");
            asm volatile(
                "cp.async.bulk.global.shared::cta.bulk_group [%0], [%1], %2;"
                :: "l"(gdst), "r"(sTile), "r"(TILE_BYTES) : "memory");
            asm volatile("cp.async.bulk.commit_group;" ::: "memory");
            asm volatile("cp.async.bulk.wait_group.read 0;" ::: "memory");
        }
        // issuing thread holds the CTA alive until the bulk read completes
    } else {
        // ---- scalar fallback for a partial tail block (unused for B=32768) ----
        const int puzCount = nPuz - basePuz;
        if (puzCount <= 0) return;
        const int nCellAct = puzCount * 81;

        for (int t = tid; t < nCellAct; t += THREADS) {
            const int pl = t / 81;
            const int rc = t - pl * 81;
            const float* p = in + (size_t)(basePuz + pl) * PUZ + rc;
            unsigned mm = 0;
            #pragma unroll
            for (int d = 0; d < 9; d++)
                mm |= ((__float_as_uint(p[d * 81]) >> 23) & 1u) << d;
            masks[t] = (int)mm;
        }
        __syncthreads();

        __shared__ int rowinfo[PPB * 9];
        if (tid < (unsigned)(puzCount * 9)) {
            const int rowBase = 9 * tid;
            int pv[9];
            #pragma unroll
            for (int k = 0; k < 9; k++) {
                const int mk = masks[rowBase + k];
                pv[k] = (__popc(mk) == 2) ? mk : 0;
            }
            int act = 0, tor = 0;
            #pragma unroll
            for (int j = 0; j < 9; j++) {
                int cc = 0;
                #pragma unroll
                for (int k = 0; k < 9; k++)
                    cc += (pv[k] == pv[j]) ? 1 : 0;
                const bool a = (pv[j] != 0) & (cc == 2);
                act |= a ? (1 << j) : 0;
                tor |= a ? pv[j] : 0;
            }
            rowinfo[tid] = tor | (act << 16);
        }
        __syncthreads();

        for (int j = tid; j < nCellAct; j += THREADS) {
            const int row = j / 9;
            const int c   = j - 9 * row;
            const int m   = masks[j];
            const int info = rowinfo[row];
            const int act  = info >> 16;
            int erase;
            if ((act >> c) & 1) {
                erase = 0;
                #pragma unroll
                for (int jj = 0; jj < 9; jj++)
                    if ((act >> jj) & 1) {
                        const int pj = masks[9 * row + jj];
                        if (pj != m) erase |= pj;
                    }
            } else {
                erase = info & 0xFFFF;
            }
            const int keep = m & ~erase;
            const int pl = j / 81;
            const int rc = j - pl * 81;
            float* p = out + (size_t)(basePuz + pl) * PUZ + rc;
            #pragma unroll
            for (int d = 0; d < 9; d++)
                p[d * 81] = ((keep >> d) & 1) ? 1.0f : 0.0f;
        }
    }
}

extern "C" void kernel_launch(void* const* d_in, const int* in_sizes, int n_in,
                              void* d_out, int out_size)
{
    const float* mask = (const float*)d_in[0];
    float* out = (float*)d_out;
    const int nPuz = in_sizes[0] / PUZ;   // 32768
    const int grid = (nPuz + PPB - 1) / PPB;
    sudoku_doubles_kernel<<<grid, THREADS>>>(mask, out, nPuz);
}

// round 9
// speedup vs baseline: 1.5892x; 1.0518x over previous
#include <cuda_runtime.h>
#include <cuda_bf16.h>
#include <cstdint>

// SudokuDigitsDoubles — exact boolean reduction ("naked pairs" row elimination).
//
// Round 9: persistent CTAs + double-buffered cp.async.bulk pipeline.
// Each CTA loops over ~7 tiles (8 puzzles each). While tile i is being
// computed/stored from buffer b, tile i+1 is already loading into buffer b^1.
// Row leaders read their 81 floats directly from the smem tile (no masks
// array, no B1 phase) and edit the tile in place only when the row has an
// active naked pair (~0.5% of rows). Buffer reuse is guarded by
// cp.async.bulk.wait_group.read before each prefetch.

static constexpr int PUZ = 729;                  // floats per puzzle
static constexpr int PPB = 8;                    // puzzles per tile
static constexpr int NF  = PPB * PUZ;            // 5832 floats per tile
static constexpr unsigned TILE_BYTES = NF * 4;   // 23328
static constexpr int THREADS = 256;
static constexpr int GRID_CTAS = 592;            // 4 per SM * 148 SMs

__device__ __forceinline__ unsigned smem_u32(const void* p) {
    unsigned a;
    asm("{ .reg .u64 t; cvta.to.shared.u64 t, %1; cvt.u32.u64 %0, t; }"
        : "=r"(a) : "l"(p));
    return a;
}

__device__ __forceinline__ void mbar_wait(unsigned bar, unsigned parity) {
    unsigned done;
    do {
        asm volatile(
            "{\n\t.reg .pred p;\n\t"
            "mbarrier.try_wait.parity.acquire.cta.shared::cta.b64 p, [%1], %2;\n\t"
            "selp.b32 %0, 1, 0, p;\n\t}"
            : "=r"(done) : "r"(bar), "r"(parity) : "memory");
    } while (!done);
}

__global__ __launch_bounds__(THREADS, 4)
void sudoku_doubles_kernel(const float* __restrict__ in,
                           float* __restrict__ out,
                           int nPuz, int nTiles)
{
    __shared__ alignas(128) float buf[2][NF];
    __shared__ alignas(8) unsigned long long mbar[2];

    const unsigned tid = threadIdx.x;
    const unsigned sBar[2] = { smem_u32(&mbar[0]), smem_u32(&mbar[1]) };
    const unsigned sBuf[2] = { smem_u32(buf[0]),   smem_u32(buf[1])   };

    if (tid == 0) {
        asm volatile("mbarrier.init.shared.b64 [%0], 1;" :: "r"(sBar[0]) : "memory");
        asm volatile("mbarrier.init.shared.b64 [%0], 1;" :: "r"(sBar[1]) : "memory");
    }
    __syncthreads();

    int ph[2] = {0, 0};            // per-buffer wait parity (uniform across CTA)
    int b = 0;

    // prologue: kick off the first tile's load
    {
        const int tile = blockIdx.x;
        if (tid == 0 && tile < nTiles) {
            const int tb = tile * PPB;
            if (tb + PPB <= nPuz) {
                asm volatile("mbarrier.arrive.expect_tx.shared.b64 _, [%0], %1;"
                             :: "r"(sBar[0]), "r"(TILE_BYTES) : "memory");
                asm volatile(
                    "cp.async.bulk.shared::cluster.global.mbarrier::complete_tx::bytes "
                    "[%0], [%1], %2, [%3];"
                    :: "r"(sBuf[0]), "l"(in + (size_t)tb * PUZ), "r"(TILE_BYTES),
                       "r"(sBar[0]) : "memory");
            }
        }
    }

    for (int tile = blockIdx.x; tile < nTiles; tile += gridDim.x, b ^= 1) {
        const int tileBase = tile * PPB;
        const bool full = (tileBase + PPB <= nPuz);

        // ---- prefetch next tile into the other buffer ----
        const int nextTile = tile + gridDim.x;
        if (tid == 0 && nextTile < nTiles) {
            const int ntb = nextTile * PPB;
            if (ntb + PPB <= nPuz) {
                // buffer b^1's previous store must have finished reading smem
                asm volatile("cp.async.bulk.wait_group.read 0;" ::: "memory");
                asm volatile("mbarrier.arrive.expect_tx.shared.b64 _, [%0], %1;"
                             :: "r"(sBar[b ^ 1]), "r"(TILE_BYTES) : "memory");
                asm volatile(
                    "cp.async.bulk.shared::cluster.global.mbarrier::complete_tx::bytes "
                    "[%0], [%1], %2, [%3];"
                    :: "r"(sBuf[b ^ 1]), "l"(in + (size_t)ntb * PUZ), "r"(TILE_BYTES),
                       "r"(sBar[b ^ 1]) : "memory");
            }
        }

        if (full) {
            // ---- wait for this tile's data ----
            mbar_wait(sBar[b], (unsigned)ph[b]);
            ph[b] ^= 1;

            // ---- 72 row leaders: logic directly on the smem tile ----
            if (tid < PPB * 9) {
                const int pl = tid / 9;
                const int r  = tid - 9 * pl;
                const unsigned* rowp =
                    reinterpret_cast<const unsigned*>(buf[b]) + pl * PUZ + r * 9;

                int m[9], pv[9];
                #pragma unroll
                for (int c = 0; c < 9; c++) {
                    unsigned mm = 0;
                    #pragma unroll
                    for (int d = 0; d < 9; d++)
                        mm |= ((rowp[d * 81 + c] >> 23) & 1u) << d;  // 1.0f vs 0.0f
                    m[c]  = (int)mm;
                    pv[c] = (__popc((unsigned)m[c]) == 2) ? m[c] : 0;
                }
                int act = 0, tor = 0;
                #pragma unroll
                for (int j = 0; j < 9; j++) {
                    int cc = 0;
                    #pragma unroll
                    for (int k = 0; k < 9; k++)
                        cc += (pv[k] == pv[j]) ? 1 : 0;
                    const bool a = (pv[j] != 0) & (cc == 2);
                    act |= a ? (1 << j) : 0;
                    tor |= a ? pv[j] : 0;
                }
                if (act) {   // rare: ~0.5% of rows
                    float* o = buf[b] + pl * PUZ + r * 9;
                    #pragma unroll
                    for (int c = 0; c < 9; c++) {
                        int erase;
                        if ((act >> c) & 1) {
                            erase = 0;
                            #pragma unroll
                            for (int j = 0; j < 9; j++)
                                if (((act >> j) & 1) && pv[j] != pv[c])
                                    erase |= pv[j];
                        } else {
                            erase = tor;
                        }
                        const int keep = m[c] & ~erase;
                        #pragma unroll
                        for (int d = 0; d < 9; d++)
                            o[d * 81 + c] = ((keep >> d) & 1) ? 1.0f : 0.0f;
                    }
                }
            }
            __syncthreads();

            // ---- bulk store this tile ----
            if (tid == 0) {
                asm volatile("fence.proxy.async.shared::cta;" ::: "memory");
                asm volatile(
                    "cp.async.bulk.global.shared::cta.bulk_group [%0], [%1], %2;"
                    :: "l"(out + (size_t)tileBase * PUZ), "r"(sBuf[b]), "r"(TILE_BYTES)
                    : "memory");
                asm volatile("cp.async.bulk.commit_group;" ::: "memory");
            }
        } else {
            // ---- partial tail tile: direct scalar path (no smem, no pipeline) ----
            const int puzCount = nPuz - tileBase;
            if (puzCount > 0 && tid < (unsigned)(puzCount * 9)) {
                const int pl = tid / 9;
                const int r  = tid - 9 * pl;
                const float* gi = in  + (size_t)(tileBase + pl) * PUZ + r * 9;
                float*       go = out + (size_t)(tileBase + pl) * PUZ + r * 9;
                int m[9], pv[9];
                #pragma unroll
                for (int c = 0; c < 9; c++) {
                    unsigned mm = 0;
                    #pragma unroll
                    for (int d = 0; d < 9; d++)
                        mm |= ((__float_as_uint(gi[d * 81 + c]) >> 23) & 1u) << d;
                    m[c]  = (int)mm;
                    pv[c] = (__popc(mm) == 2) ? m[c] : 0;
                }
                int act = 0, tor = 0;
                #pragma unroll
                for (int j = 0; j < 9; j++) {
                    int cc = 0;
                    #pragma unroll
                    for (int k = 0; k < 9; k++)
                        cc += (pv[k] == pv[j]) ? 1 : 0;
                    const bool a = (pv[j] != 0) & (cc == 2);
                    act |= a ? (1 << j) : 0;
                    tor |= a ? pv[j] : 0;
                }
                #pragma unroll
                for (int c = 0; c < 9; c++) {
                    int erase;
                    if ((act >> c) & 1) {
                        erase = 0;
                        #pragma unroll
                        for (int j = 0; j < 9; j++)
                            if (((act >> j) & 1) && pv[j] != pv[c])
                                erase |= pv[j];
                    } else {
                        erase = tor;
                    }
                    const int keep = m[c] & ~erase;
                    #pragma unroll
                    for (int d = 0; d < 9; d++)
                        go[d * 81 + c] = ((keep >> d) & 1) ? 1.0f : 0.0f;
                }
            }
        }
    }

    // drain: last store must finish reading smem before the CTA exits
    if (tid == 0)
        asm volatile("cp.async.bulk.wait_group.read 0;" ::: "memory");
}

extern "C" void kernel_launch(void* const* d_in, const int* in_sizes, int n_in,
                              void* d_out, int out_size)
{
    const float* mask = (const float*)d_in[0];
    float* out = (float*)d_out;
    const int nPuz = in_sizes[0] / PUZ;                 // 32768
    const int nTiles = (nPuz + PPB - 1) / PPB;          // 4096
    const int grid = (nTiles < GRID_CTAS) ? nTiles : GRID_CTAS;
    sudoku_doubles_kernel<<<grid, THREADS>>>(mask, out, nPuz, nTiles);
}